// round 2
// baseline (speedup 1.0000x reference)
#include <cuda_runtime.h>

#define NN    100000
#define DIN   128
#define DHID  64
#define DOUT  6
#define EMAX  1600000
#define EPMAX (EMAX + NN)
#define NEG   0.2f

// ---------------- static device scratch (no allocations allowed) ----------------
__device__ float g_h1[(size_t)NN * DHID];    // x @ W1
__device__ float g_out1[(size_t)NN * DHID];  // elu(gat1) -> layer2 input
__device__ float g_h2[(size_t)NN * DOUT];    // out1 @ W2
__device__ float g_s1[NN], g_d1[NN];
__device__ float g_s2[NN], g_d2[NN];
__device__ int   g_deg[NN];
__device__ int   g_offs[NN + 1];
__device__ int   g_cursor[NN];
__device__ int   g_csr[EPMAX];               // src indices grouped by dst
__device__ float g_e[EPMAX];                 // per-edge logit scratch (CSR order)
__device__ int   g_is64;                     // edge_index dtype flag

// ---------------- dtype detection ----------------
// If edge_index is int64 (values < 2^31), every odd 32-bit word is 0.
// If int32, odd words are random indices in [0, 100000) -> almost surely nonzero.
__global__ void k_detect(const int* __restrict__ w, int n_words) {
    __shared__ int nz;
    if (threadIdx.x == 0) nz = 0;
    __syncthreads();
    for (int i = threadIdx.x; i < 2048; i += blockDim.x) {
        int idx = 2 * i + 1;
        if (idx < n_words && w[idx] != 0) atomicAdd(&nz, 1);
    }
    __syncthreads();
    if (threadIdx.x == 0) g_is64 = (nz == 0) ? 1 : 0;
}

__device__ __forceinline__ int read_ei(const void* p, long long i) {
    if (g_is64) return (int)((const long long*)p)[i];
    return ((const int*)p)[i];
}

// ---------------- CSR build ----------------
__global__ void k_init_deg() {
    int i = blockIdx.x * blockDim.x + threadIdx.x;
    if (i < NN) g_deg[i] = 1;  // self loop
}

__global__ void k_hist(const void* __restrict__ ei, int E) {
    int i = blockIdx.x * blockDim.x + threadIdx.x;
    if (i < E) {
        int d = read_ei(ei, (long long)E + i);
        if (d >= 0 && d < NN) atomicAdd(&g_deg[d], 1);
    }
}

// single-block exclusive scan of g_deg -> g_offs, also copies to g_cursor
__global__ void k_scan() {
    __shared__ int sh[1024];
    int t = threadIdx.x;
    int chunk = (NN + 1023) / 1024;
    int beg = t * chunk;
    int end = min(beg + chunk, NN);
    int sum = 0;
    for (int i = beg; i < end; ++i) sum += g_deg[i];
    sh[t] = sum;
    __syncthreads();
    for (int off = 1; off < 1024; off <<= 1) {
        int v = (t >= off) ? sh[t - off] : 0;
        __syncthreads();
        sh[t] += v;
        __syncthreads();
    }
    int running = sh[t] - sum;  // exclusive prefix
    for (int i = beg; i < end; ++i) {
        g_offs[i]   = running;
        g_cursor[i] = running;
        running += g_deg[i];
    }
    if (t == 0) g_offs[NN] = sh[1023];
}

__global__ void k_fill(const void* __restrict__ ei, int E, int EP) {
    int i = blockIdx.x * blockDim.x + threadIdx.x;
    if (i >= EP) return;
    int s, d;
    if (i < E) {
        s = read_ei(ei, i);
        d = read_ei(ei, (long long)E + i);
    } else {
        s = d = i - E;  // self loop
    }
    if (d < 0 || d >= NN || s < 0 || s >= NN) return;
    int pos = atomicAdd(&g_cursor[d], 1);
    g_csr[pos] = s;
}

// ---------------- GEMM1: h1 = x @ W1   (100000x128 @ 128x64) ----------------
__global__ void k_gemm1(const float* __restrict__ x, const float* __restrict__ W) {
    __shared__ float xsT[64][68];  // [k_local][m_local], padded
    __shared__ float ws[64][64];   // [k_local][n]
    int t  = threadIdx.x;
    int m0 = blockIdx.x * 64;
    int tx = t & 15;   // n quad
    int ty = t >> 4;   // m quad
    float acc[4][4];
#pragma unroll
    for (int i = 0; i < 4; ++i)
#pragma unroll
        for (int j = 0; j < 4; ++j) acc[i][j] = 0.f;

    for (int ks = 0; ks < DIN; ks += 64) {
#pragma unroll
        for (int it = 0; it < 4; ++it) {
            int idx = t + it * 256;       // 0..1023
            int row = idx >> 4;           // 0..63
            int c4  = idx & 15;           // float4 index along k
            float4 v = make_float4(0.f, 0.f, 0.f, 0.f);
            if (m0 + row < NN)
                v = *(const float4*)&x[(size_t)(m0 + row) * DIN + ks + c4 * 4];
            xsT[c4 * 4 + 0][row] = v.x;
            xsT[c4 * 4 + 1][row] = v.y;
            xsT[c4 * 4 + 2][row] = v.z;
            xsT[c4 * 4 + 3][row] = v.w;
        }
#pragma unroll
        for (int it = 0; it < 4; ++it) {
            int idx = t + it * 256;
            int kr  = idx >> 4;
            int c4  = idx & 15;
            *(float4*)&ws[kr][c4 * 4] =
                *(const float4*)&W[(size_t)(ks + kr) * DHID + c4 * 4];
        }
        __syncthreads();
#pragma unroll 8
        for (int k = 0; k < 64; ++k) {
            float4 a = *(const float4*)&xsT[k][ty * 4];
            float4 b = *(const float4*)&ws[k][tx * 4];
            acc[0][0] += a.x * b.x; acc[0][1] += a.x * b.y; acc[0][2] += a.x * b.z; acc[0][3] += a.x * b.w;
            acc[1][0] += a.y * b.x; acc[1][1] += a.y * b.y; acc[1][2] += a.y * b.z; acc[1][3] += a.y * b.w;
            acc[2][0] += a.z * b.x; acc[2][1] += a.z * b.y; acc[2][2] += a.z * b.z; acc[2][3] += a.z * b.w;
            acc[3][0] += a.w * b.x; acc[3][1] += a.w * b.y; acc[3][2] += a.w * b.z; acc[3][3] += a.w * b.w;
        }
        __syncthreads();
    }
#pragma unroll
    for (int i = 0; i < 4; ++i) {
        int row = m0 + ty * 4 + i;
        if (row < NN) {
#pragma unroll
            for (int j = 0; j < 4; ++j)
                g_h1[(size_t)row * DHID + tx * 4 + j] = acc[i][j];
        }
    }
}

// s1/d1 per node: dot(h1[v], a_src/a_dst), warp per node
__global__ void k_sd64(const float* __restrict__ as, const float* __restrict__ ad) {
    int w    = (blockIdx.x * blockDim.x + threadIdx.x) >> 5;
    int lane = threadIdx.x & 31;
    if (w >= NN) return;
    float h0 = g_h1[(size_t)w * DHID + lane];
    float h1 = g_h1[(size_t)w * DHID + 32 + lane];
    float ps = h0 * as[lane] + h1 * as[lane + 32];
    float pd = h0 * ad[lane] + h1 * ad[lane + 32];
#pragma unroll
    for (int o = 16; o; o >>= 1) {
        ps += __shfl_xor_sync(0xffffffffu, ps, o);
        pd += __shfl_xor_sync(0xffffffffu, pd, o);
    }
    if (lane == 0) { g_s1[w] = ps; g_d1[w] = pd; }
}

// ---------------- layer-1 GAT: softmax + aggregate, warp per dst node ----------------
__global__ void k_edge64(const float* __restrict__ bias) {
    int w    = (blockIdx.x * blockDim.x + threadIdx.x) >> 5;
    int lane = threadIdx.x & 31;
    if (w >= NN) return;
    int beg = g_offs[w], end = g_offs[w + 1];
    float dv = g_d1[w];

    // pass 1: logits + max
    float m = -1e30f;
    for (int j = beg + lane; j < end; j += 32) {
        int si  = g_csr[j];
        float e = g_s1[si] + dv;
        e = (e > 0.f) ? e : NEG * e;
        g_e[j] = e;
        m = fmaxf(m, e);
    }
#pragma unroll
    for (int o = 16; o; o >>= 1) m = fmaxf(m, __shfl_xor_sync(0xffffffffu, m, o));

    // pass 2: exp, denom, weighted gather-accumulate
    float denom = 0.f, acc0 = 0.f, acc1 = 0.f;
    for (int base = beg; base < end; base += 32) {
        int j = base + lane;
        float ex = 0.f;
        int si = 0;
        if (j < end) { ex = __expf(g_e[j] - m); si = g_csr[j]; }
        denom += ex;
        int cnt = min(32, end - base);
        int t = 0;
        for (; t + 4 <= cnt; t += 4) {
            float e0 = __shfl_sync(0xffffffffu, ex, t + 0);
            float e1 = __shfl_sync(0xffffffffu, ex, t + 1);
            float e2 = __shfl_sync(0xffffffffu, ex, t + 2);
            float e3 = __shfl_sync(0xffffffffu, ex, t + 3);
            int   s0 = __shfl_sync(0xffffffffu, si, t + 0);
            int   s1 = __shfl_sync(0xffffffffu, si, t + 1);
            int   s2 = __shfl_sync(0xffffffffu, si, t + 2);
            int   s3 = __shfl_sync(0xffffffffu, si, t + 3);
            const float* p0 = g_h1 + (size_t)s0 * DHID;
            const float* p1 = g_h1 + (size_t)s1 * DHID;
            const float* p2 = g_h1 + (size_t)s2 * DHID;
            const float* p3 = g_h1 + (size_t)s3 * DHID;
            float x00 = p0[lane], x01 = p0[lane + 32];
            float x10 = p1[lane], x11 = p1[lane + 32];
            float x20 = p2[lane], x21 = p2[lane + 32];
            float x30 = p3[lane], x31 = p3[lane + 32];
            acc0 = fmaf(e0, x00, acc0); acc1 = fmaf(e0, x01, acc1);
            acc0 = fmaf(e1, x10, acc0); acc1 = fmaf(e1, x11, acc1);
            acc0 = fmaf(e2, x20, acc0); acc1 = fmaf(e2, x21, acc1);
            acc0 = fmaf(e3, x30, acc0); acc1 = fmaf(e3, x31, acc1);
        }
        for (; t < cnt; ++t) {
            float ej = __shfl_sync(0xffffffffu, ex, t);
            int   sj = __shfl_sync(0xffffffffu, si, t);
            const float* p = g_h1 + (size_t)sj * DHID;
            acc0 = fmaf(ej, p[lane], acc0);
            acc1 = fmaf(ej, p[lane + 32], acc1);
        }
    }
#pragma unroll
    for (int o = 16; o; o >>= 1) denom += __shfl_xor_sync(0xffffffffu, denom, o);

    float inv = 1.f / denom;
    float o0 = acc0 * inv + bias[lane];
    float o1 = acc1 * inv + bias[lane + 32];
    // ELU (alpha=1)
    o0 = (o0 > 0.f) ? o0 : expm1f(o0);
    o1 = (o1 > 0.f) ? o1 : expm1f(o1);
    g_out1[(size_t)w * DHID + lane]      = o0;
    g_out1[(size_t)w * DHID + 32 + lane] = o1;
}

// ---------------- layer 2: h2 = out1 @ W2 + s2/d2, warp per node ----------------
__global__ void k_gemm2sd(const float* __restrict__ W2,
                          const float* __restrict__ as, const float* __restrict__ ad) {
    int w    = (blockIdx.x * blockDim.x + threadIdx.x) >> 5;
    int lane = threadIdx.x & 31;
    if (w >= NN) return;
    float h0 = g_out1[(size_t)w * DHID + lane];
    float h1 = g_out1[(size_t)w * DHID + 32 + lane];
    float p[DOUT];
#pragma unroll
    for (int c = 0; c < DOUT; ++c)
        p[c] = h0 * W2[lane * DOUT + c] + h1 * W2[(lane + 32) * DOUT + c];
#pragma unroll
    for (int c = 0; c < DOUT; ++c)
#pragma unroll
        for (int o = 16; o; o >>= 1) p[c] += __shfl_xor_sync(0xffffffffu, p[c], o);
    if (lane == 0) {
        float s = 0.f, d = 0.f;
#pragma unroll
        for (int c = 0; c < DOUT; ++c) {
            g_h2[(size_t)w * DOUT + c] = p[c];
            s += p[c] * as[c];
            d += p[c] * ad[c];
        }
        g_s2[w] = s;
        g_d2[w] = d;
    }
}

// ---------------- layer-2 GAT (C=6): warp per dst node, per-lane edges ----------------
__global__ void k_edge6(const float* __restrict__ b2, float* __restrict__ out) {
    int w    = (blockIdx.x * blockDim.x + threadIdx.x) >> 5;
    int lane = threadIdx.x & 31;
    if (w >= NN) return;
    int beg = g_offs[w], end = g_offs[w + 1];
    float dv = g_d2[w];

    float m = -1e30f;
    for (int j = beg + lane; j < end; j += 32) {
        int si  = g_csr[j];
        float e = g_s2[si] + dv;
        e = (e > 0.f) ? e : NEG * e;
        g_e[j] = e;
        m = fmaxf(m, e);
    }
#pragma unroll
    for (int o = 16; o; o >>= 1) m = fmaxf(m, __shfl_xor_sync(0xffffffffu, m, o));

    float denom = 0.f;
    float a0 = 0.f, a1 = 0.f, a2 = 0.f, a3 = 0.f, a4 = 0.f, a5 = 0.f;
    for (int j = beg + lane; j < end; j += 32) {
        int si   = g_csr[j];
        float ex = __expf(g_e[j] - m);
        denom += ex;
        const float2* hp = (const float2*)g_h2 + (size_t)si * 3;
        float2 v0 = hp[0], v1 = hp[1], v2 = hp[2];
        a0 = fmaf(ex, v0.x, a0); a1 = fmaf(ex, v0.y, a1);
        a2 = fmaf(ex, v1.x, a2); a3 = fmaf(ex, v1.y, a3);
        a4 = fmaf(ex, v2.x, a4); a5 = fmaf(ex, v2.y, a5);
    }
#pragma unroll
    for (int o = 16; o; o >>= 1) {
        denom += __shfl_xor_sync(0xffffffffu, denom, o);
        a0 += __shfl_xor_sync(0xffffffffu, a0, o);
        a1 += __shfl_xor_sync(0xffffffffu, a1, o);
        a2 += __shfl_xor_sync(0xffffffffu, a2, o);
        a3 += __shfl_xor_sync(0xffffffffu, a3, o);
        a4 += __shfl_xor_sync(0xffffffffu, a4, o);
        a5 += __shfl_xor_sync(0xffffffffu, a5, o);
    }
    if (lane == 0) {
        float inv = 1.f / denom;
        out[(size_t)w * DOUT + 0] = a0 * inv + b2[0];
        out[(size_t)w * DOUT + 1] = a1 * inv + b2[1];
        out[(size_t)w * DOUT + 2] = a2 * inv + b2[2];
        out[(size_t)w * DOUT + 3] = a3 * inv + b2[3];
        out[(size_t)w * DOUT + 4] = a4 * inv + b2[4];
        out[(size_t)w * DOUT + 5] = a5 * inv + b2[5];
    }
}

// ---------------- launch ----------------
extern "C" void kernel_launch(void* const* d_in, const int* in_sizes, int n_in,
                              void* d_out, int out_size) {
    const float* x      = (const float*)d_in[0];
    const void*  ei     = d_in[1];
    const float* W1     = (const float*)d_in[2];
    const float* a_src1 = (const float*)d_in[3];
    const float* a_dst1 = (const float*)d_in[4];
    const float* b1     = (const float*)d_in[5];
    const float* W2     = (const float*)d_in[6];
    const float* a_src2 = (const float*)d_in[7];
    const float* a_dst2 = (const float*)d_in[8];
    const float* b2     = (const float*)d_in[9];
    float*       out    = (float*)d_out;

    int E  = in_sizes[1] / 2;
    int EP = E + NN;
    // number of 32-bit words if buffer were int32 (lower bound either way)
    int n_words = in_sizes[1];

    k_detect<<<1, 256>>>((const int*)ei, n_words);

    // CSR build
    k_init_deg<<<(NN + 255) / 256, 256>>>();
    k_hist<<<(E + 255) / 256, 256>>>(ei, E);
    k_scan<<<1, 1024>>>();
    k_fill<<<(EP + 255) / 256, 256>>>(ei, E, EP);

    // layer 1
    k_gemm1<<<(NN + 63) / 64, 256>>>(x, W1);
    int warp_blocks = (NN * 32 + 255) / 256;
    k_sd64<<<warp_blocks, 256>>>(a_src1, a_dst1);
    k_edge64<<<warp_blocks, 256>>>(b1);

    // layer 2
    k_gemm2sd<<<warp_blocks, 256>>>(W2, a_src2, a_dst2);
    k_edge6<<<warp_blocks, 256>>>(b2, out);
}

// round 3
// speedup vs baseline: 1.6361x; 1.6361x over previous
#include <cuda_runtime.h>

#define NN    100000
#define DIN   128
#define DHID  64
#define DOUT  6
#define EMAX  1600000
#define EPMAX (EMAX + NN)
#define NEG   0.2f

#define SCAN_BLK   1024
#define SCAN_NBLK  ((NN + SCAN_BLK - 1) / SCAN_BLK)   // 98

// ---------------- static device scratch ----------------
__device__ float g_h1[(size_t)NN * DHID];
__device__ float g_out1[(size_t)NN * DHID];
__device__ float g_h2[(size_t)NN * DOUT];
__device__ float g_s1[NN], g_d1[NN];
__device__ float g_s2[NN], g_d2[NN];
__device__ int   g_deg[NN];
__device__ int   g_offs[NN + 1];
__device__ int   g_cursor[NN];
__device__ int   g_csr[EPMAX];
__device__ float g_e[EPMAX];
__device__ int   g_is64;
__device__ int   g_bsum[SCAN_NBLK];
__device__ int   g_boff[SCAN_NBLK];

// ---------------- dtype detection ----------------
__global__ void k_detect(const int* __restrict__ w, int n_words) {
    __shared__ int nz;
    if (threadIdx.x == 0) nz = 0;
    __syncthreads();
    for (int i = threadIdx.x; i < 2048; i += blockDim.x) {
        int idx = 2 * i + 1;
        if (idx < n_words && w[idx] != 0) atomicAdd(&nz, 1);
    }
    __syncthreads();
    if (threadIdx.x == 0) g_is64 = (nz == 0) ? 1 : 0;
}

__device__ __forceinline__ int read_ei(const void* p, long long i) {
    if (g_is64) return (int)((const long long*)p)[i];
    return ((const int*)p)[i];
}

// ---------------- CSR build ----------------
__global__ void k_init_deg() {
    int i = blockIdx.x * blockDim.x + threadIdx.x;
    if (i < NN) g_deg[i] = 1;  // self loop
}

__global__ void k_hist(const void* __restrict__ ei, int E) {
    int i = blockIdx.x * blockDim.x + threadIdx.x;
    if (i < E) {
        int d = read_ei(ei, (long long)E + i);
        if (d >= 0 && d < NN) atomicAdd(&g_deg[d], 1);
    }
}

// ---- 3-phase full-chip exclusive scan of g_deg -> g_offs / g_cursor ----
__global__ void k_scan_partial() {
    __shared__ int sh[SCAN_BLK];
    int t = threadIdx.x;
    int i = blockIdx.x * SCAN_BLK + t;
    int v = (i < NN) ? g_deg[i] : 0;
    sh[t] = v;
    __syncthreads();
    for (int off = SCAN_BLK / 2; off > 0; off >>= 1) {
        if (t < off) sh[t] += sh[t + off];
        __syncthreads();
    }
    if (t == 0) g_bsum[blockIdx.x] = sh[0];
}

__global__ void k_scan_bsum() {
    __shared__ int sh[128];
    int t = threadIdx.x;  // 128 threads, SCAN_NBLK<=128
    int v = (t < SCAN_NBLK) ? g_bsum[t] : 0;
    sh[t] = v;
    __syncthreads();
    for (int off = 1; off < 128; off <<= 1) {
        int u = (t >= off) ? sh[t - off] : 0;
        __syncthreads();
        sh[t] += u;
        __syncthreads();
    }
    if (t < SCAN_NBLK) g_boff[t] = sh[t] - v;  // exclusive
    if (t == 127) g_offs[NN] = sh[127];
}

__global__ void k_scan_final() {
    __shared__ int sh[SCAN_BLK];
    int t = threadIdx.x;
    int i = blockIdx.x * SCAN_BLK + t;
    int v = (i < NN) ? g_deg[i] : 0;
    sh[t] = v;
    __syncthreads();
    for (int off = 1; off < SCAN_BLK; off <<= 1) {
        int u = (t >= off) ? sh[t - off] : 0;
        __syncthreads();
        sh[t] += u;
        __syncthreads();
    }
    if (i < NN) {
        int ex = sh[t] - v + g_boff[blockIdx.x];
        g_offs[i]   = ex;
        g_cursor[i] = ex;
    }
}

__global__ void k_fill(const void* __restrict__ ei, int E, int EP) {
    int i = blockIdx.x * blockDim.x + threadIdx.x;
    if (i >= EP) return;
    int s, d;
    if (i < E) {
        s = read_ei(ei, i);
        d = read_ei(ei, (long long)E + i);
    } else {
        s = d = i - E;
    }
    if (d < 0 || d >= NN || s < 0 || s >= NN) return;
    int pos = atomicAdd(&g_cursor[d], 1);
    g_csr[pos] = s;
}

// ---------------- GEMM1: h1 = x @ W1 ----------------
__global__ void k_gemm1(const float* __restrict__ x, const float* __restrict__ W) {
    __shared__ float xsT[64][68];
    __shared__ float ws[64][64];
    int t  = threadIdx.x;
    int m0 = blockIdx.x * 64;
    int tx = t & 15;
    int ty = t >> 4;
    float acc[4][4];
#pragma unroll
    for (int i = 0; i < 4; ++i)
#pragma unroll
        for (int j = 0; j < 4; ++j) acc[i][j] = 0.f;

    for (int ks = 0; ks < DIN; ks += 64) {
#pragma unroll
        for (int it = 0; it < 4; ++it) {
            int idx = t + it * 256;
            int row = idx >> 4;
            int c4  = idx & 15;
            float4 v = make_float4(0.f, 0.f, 0.f, 0.f);
            if (m0 + row < NN)
                v = *(const float4*)&x[(size_t)(m0 + row) * DIN + ks + c4 * 4];
            xsT[c4 * 4 + 0][row] = v.x;
            xsT[c4 * 4 + 1][row] = v.y;
            xsT[c4 * 4 + 2][row] = v.z;
            xsT[c4 * 4 + 3][row] = v.w;
        }
#pragma unroll
        for (int it = 0; it < 4; ++it) {
            int idx = t + it * 256;
            int kr  = idx >> 4;
            int c4  = idx & 15;
            *(float4*)&ws[kr][c4 * 4] =
                *(const float4*)&W[(size_t)(ks + kr) * DHID + c4 * 4];
        }
        __syncthreads();
#pragma unroll 8
        for (int k = 0; k < 64; ++k) {
            float4 a = *(const float4*)&xsT[k][ty * 4];
            float4 b = *(const float4*)&ws[k][tx * 4];
            acc[0][0] += a.x * b.x; acc[0][1] += a.x * b.y; acc[0][2] += a.x * b.z; acc[0][3] += a.x * b.w;
            acc[1][0] += a.y * b.x; acc[1][1] += a.y * b.y; acc[1][2] += a.y * b.z; acc[1][3] += a.y * b.w;
            acc[2][0] += a.z * b.x; acc[2][1] += a.z * b.y; acc[2][2] += a.z * b.z; acc[2][3] += a.z * b.w;
            acc[3][0] += a.w * b.x; acc[3][1] += a.w * b.y; acc[3][2] += a.w * b.z; acc[3][3] += a.w * b.w;
        }
        __syncthreads();
    }
#pragma unroll
    for (int i = 0; i < 4; ++i) {
        int row = m0 + ty * 4 + i;
        if (row < NN) {
#pragma unroll
            for (int j = 0; j < 4; ++j)
                g_h1[(size_t)row * DHID + tx * 4 + j] = acc[i][j];
        }
    }
}

// s1/d1 per node
__global__ void k_sd64(const float* __restrict__ as, const float* __restrict__ ad) {
    int w    = (blockIdx.x * blockDim.x + threadIdx.x) >> 5;
    int lane = threadIdx.x & 31;
    if (w >= NN) return;
    float h0 = g_h1[(size_t)w * DHID + lane];
    float h1 = g_h1[(size_t)w * DHID + 32 + lane];
    float ps = h0 * as[lane] + h1 * as[lane + 32];
    float pd = h0 * ad[lane] + h1 * ad[lane + 32];
#pragma unroll
    for (int o = 16; o; o >>= 1) {
        ps += __shfl_xor_sync(0xffffffffu, ps, o);
        pd += __shfl_xor_sync(0xffffffffu, pd, o);
    }
    if (lane == 0) { g_s1[w] = ps; g_d1[w] = pd; }
}

// ---------------- layer-1 GAT: warp per dst node ----------------
__global__ void k_edge64(const float* __restrict__ bias) {
    int w    = (blockIdx.x * blockDim.x + threadIdx.x) >> 5;
    int lane = threadIdx.x & 31;
    if (w >= NN) return;
    int beg = g_offs[w], end = g_offs[w + 1];
    float dv = g_d1[w];

    float m = -1e30f;
    for (int j = beg + lane; j < end; j += 32) {
        int si  = g_csr[j];
        float e = g_s1[si] + dv;
        e = (e > 0.f) ? e : NEG * e;
        g_e[j] = e;
        m = fmaxf(m, e);
    }
#pragma unroll
    for (int o = 16; o; o >>= 1) m = fmaxf(m, __shfl_xor_sync(0xffffffffu, m, o));

    float denom = 0.f, acc0 = 0.f, acc1 = 0.f;
    for (int base = beg; base < end; base += 32) {
        int j = base + lane;
        float ex = 0.f;
        int si = 0;
        if (j < end) { ex = __expf(g_e[j] - m); si = g_csr[j]; }
        denom += ex;
        int cnt = min(32, end - base);
        int t = 0;
        for (; t + 4 <= cnt; t += 4) {
            float e0 = __shfl_sync(0xffffffffu, ex, t + 0);
            float e1 = __shfl_sync(0xffffffffu, ex, t + 1);
            float e2 = __shfl_sync(0xffffffffu, ex, t + 2);
            float e3 = __shfl_sync(0xffffffffu, ex, t + 3);
            int   s0 = __shfl_sync(0xffffffffu, si, t + 0);
            int   s1 = __shfl_sync(0xffffffffu, si, t + 1);
            int   s2 = __shfl_sync(0xffffffffu, si, t + 2);
            int   s3 = __shfl_sync(0xffffffffu, si, t + 3);
            const float* p0 = g_h1 + (size_t)s0 * DHID;
            const float* p1 = g_h1 + (size_t)s1 * DHID;
            const float* p2 = g_h1 + (size_t)s2 * DHID;
            const float* p3 = g_h1 + (size_t)s3 * DHID;
            float x00 = p0[lane], x01 = p0[lane + 32];
            float x10 = p1[lane], x11 = p1[lane + 32];
            float x20 = p2[lane], x21 = p2[lane + 32];
            float x30 = p3[lane], x31 = p3[lane + 32];
            acc0 = fmaf(e0, x00, acc0); acc1 = fmaf(e0, x01, acc1);
            acc0 = fmaf(e1, x10, acc0); acc1 = fmaf(e1, x11, acc1);
            acc0 = fmaf(e2, x20, acc0); acc1 = fmaf(e2, x21, acc1);
            acc0 = fmaf(e3, x30, acc0); acc1 = fmaf(e3, x31, acc1);
        }
        for (; t < cnt; ++t) {
            float ej = __shfl_sync(0xffffffffu, ex, t);
            int   sj = __shfl_sync(0xffffffffu, si, t);
            const float* p = g_h1 + (size_t)sj * DHID;
            acc0 = fmaf(ej, p[lane], acc0);
            acc1 = fmaf(ej, p[lane + 32], acc1);
        }
    }
#pragma unroll
    for (int o = 16; o; o >>= 1) denom += __shfl_xor_sync(0xffffffffu, denom, o);

    float inv = 1.f / denom;
    float o0 = acc0 * inv + bias[lane];
    float o1 = acc1 * inv + bias[lane + 32];
    o0 = (o0 > 0.f) ? o0 : expm1f(o0);
    o1 = (o1 > 0.f) ? o1 : expm1f(o1);
    g_out1[(size_t)w * DHID + lane]      = o0;
    g_out1[(size_t)w * DHID + 32 + lane] = o1;
}

// ---------------- layer 2: h2 = out1 @ W2 + s2/d2 ----------------
__global__ void k_gemm2sd(const float* __restrict__ W2,
                          const float* __restrict__ as, const float* __restrict__ ad) {
    int w    = (blockIdx.x * blockDim.x + threadIdx.x) >> 5;
    int lane = threadIdx.x & 31;
    if (w >= NN) return;
    float h0 = g_out1[(size_t)w * DHID + lane];
    float h1 = g_out1[(size_t)w * DHID + 32 + lane];
    float p[DOUT];
#pragma unroll
    for (int c = 0; c < DOUT; ++c)
        p[c] = h0 * W2[lane * DOUT + c] + h1 * W2[(lane + 32) * DOUT + c];
#pragma unroll
    for (int c = 0; c < DOUT; ++c)
#pragma unroll
        for (int o = 16; o; o >>= 1) p[c] += __shfl_xor_sync(0xffffffffu, p[c], o);
    if (lane == 0) {
        float s = 0.f, d = 0.f;
#pragma unroll
        for (int c = 0; c < DOUT; ++c) {
            g_h2[(size_t)w * DOUT + c] = p[c];
            s += p[c] * as[c];
            d += p[c] * ad[c];
        }
        g_s2[w] = s;
        g_d2[w] = d;
    }
}

// ---------------- layer-2 GAT (C=6) ----------------
__global__ void k_edge6(const float* __restrict__ b2, float* __restrict__ out) {
    int w    = (blockIdx.x * blockDim.x + threadIdx.x) >> 5;
    int lane = threadIdx.x & 31;
    if (w >= NN) return;
    int beg = g_offs[w], end = g_offs[w + 1];
    float dv = g_d2[w];

    float m = -1e30f;
    for (int j = beg + lane; j < end; j += 32) {
        int si  = g_csr[j];
        float e = g_s2[si] + dv;
        e = (e > 0.f) ? e : NEG * e;
        g_e[j] = e;
        m = fmaxf(m, e);
    }
#pragma unroll
    for (int o = 16; o; o >>= 1) m = fmaxf(m, __shfl_xor_sync(0xffffffffu, m, o));

    float denom = 0.f;
    float a0 = 0.f, a1 = 0.f, a2 = 0.f, a3 = 0.f, a4 = 0.f, a5 = 0.f;
    for (int j = beg + lane; j < end; j += 32) {
        int si   = g_csr[j];
        float ex = __expf(g_e[j] - m);
        denom += ex;
        const float2* hp = (const float2*)g_h2 + (size_t)si * 3;
        float2 v0 = hp[0], v1 = hp[1], v2 = hp[2];
        a0 = fmaf(ex, v0.x, a0); a1 = fmaf(ex, v0.y, a1);
        a2 = fmaf(ex, v1.x, a2); a3 = fmaf(ex, v1.y, a3);
        a4 = fmaf(ex, v2.x, a4); a5 = fmaf(ex, v2.y, a5);
    }
#pragma unroll
    for (int o = 16; o; o >>= 1) {
        denom += __shfl_xor_sync(0xffffffffu, denom, o);
        a0 += __shfl_xor_sync(0xffffffffu, a0, o);
        a1 += __shfl_xor_sync(0xffffffffu, a1, o);
        a2 += __shfl_xor_sync(0xffffffffu, a2, o);
        a3 += __shfl_xor_sync(0xffffffffu, a3, o);
        a4 += __shfl_xor_sync(0xffffffffu, a4, o);
        a5 += __shfl_xor_sync(0xffffffffu, a5, o);
    }
    if (lane == 0) {
        float inv = 1.f / denom;
        out[(size_t)w * DOUT + 0] = a0 * inv + b2[0];
        out[(size_t)w * DOUT + 1] = a1 * inv + b2[1];
        out[(size_t)w * DOUT + 2] = a2 * inv + b2[2];
        out[(size_t)w * DOUT + 3] = a3 * inv + b2[3];
        out[(size_t)w * DOUT + 4] = a4 * inv + b2[4];
        out[(size_t)w * DOUT + 5] = a5 * inv + b2[5];
    }
}

// ---------------- launch ----------------
extern "C" void kernel_launch(void* const* d_in, const int* in_sizes, int n_in,
                              void* d_out, int out_size) {
    const float* x      = (const float*)d_in[0];
    const void*  ei     = d_in[1];
    const float* W1     = (const float*)d_in[2];
    const float* a_src1 = (const float*)d_in[3];
    const float* a_dst1 = (const float*)d_in[4];
    const float* b1     = (const float*)d_in[5];
    const float* W2     = (const float*)d_in[6];
    const float* a_src2 = (const float*)d_in[7];
    const float* a_dst2 = (const float*)d_in[8];
    const float* b2     = (const float*)d_in[9];
    float*       out    = (float*)d_out;

    int E  = in_sizes[1] / 2;
    int EP = E + NN;
    int n_words = in_sizes[1];

    k_detect<<<1, 256>>>((const int*)ei, n_words);

    // CSR build
    k_init_deg<<<(NN + 255) / 256, 256>>>();
    k_hist<<<(E + 255) / 256, 256>>>(ei, E);
    k_scan_partial<<<SCAN_NBLK, SCAN_BLK>>>();
    k_scan_bsum<<<1, 128>>>();
    k_scan_final<<<SCAN_NBLK, SCAN_BLK>>>();
    k_fill<<<(EP + 255) / 256, 256>>>(ei, E, EP);

    // layer 1
    k_gemm1<<<(NN + 63) / 64, 256>>>(x, W1);
    int warp_blocks = (NN * 32 + 255) / 256;
    k_sd64<<<warp_blocks, 256>>>(a_src1, a_dst1);
    k_edge64<<<warp_blocks, 256>>>(b1);

    // layer 2
    k_gemm2sd<<<warp_blocks, 256>>>(W2, a_src2, a_dst2);
    k_edge6<<<warp_blocks, 256>>>(b2, out);
}

// round 6
// speedup vs baseline: 1.8773x; 1.1474x over previous
#include <cuda_runtime.h>

#define NN    100000
#define DIN   128
#define DHID  64
#define DOUT  6
#define EMAX  1600000
#define EPMAX (EMAX + NN)
#define NEG   0.2f

#define SCAN_BLK   1024
#define SCAN_NBLK  ((NN + SCAN_BLK - 1) / SCAN_BLK)   // 98

// ---------------- static device scratch ----------------
__device__ float g_h1[(size_t)NN * DHID];
__device__ float g_out1[(size_t)NN * DHID];
__device__ float g_h2[(size_t)NN * DOUT];
__device__ float g_s1[NN], g_d1[NN];
__device__ float g_s2[NN], g_d2[NN];
__device__ int   g_deg[NN];
__device__ int   g_offs[NN + 1];
__device__ int   g_cursor[NN];
__device__ int   g_csr[EPMAX];
__device__ float g_e[EPMAX];
__device__ int   g_is64;
__device__ int   g_bsum[SCAN_NBLK];
__device__ int   g_boff[SCAN_NBLK];

// ---------------- tf32 helpers ----------------
__device__ __forceinline__ unsigned f2tf32(float f) {
    unsigned r;
    asm("cvt.rna.tf32.f32 %0, %1;" : "=r"(r) : "f"(f));
    return r;
}

__device__ __forceinline__ void mma_tf32(float* c, const unsigned* a, const unsigned* b) {
    asm volatile(
        "mma.sync.aligned.m16n8k8.row.col.f32.tf32.tf32.f32 "
        "{%0,%1,%2,%3}, {%4,%5,%6,%7}, {%8,%9}, {%0,%1,%2,%3};"
        : "+f"(c[0]), "+f"(c[1]), "+f"(c[2]), "+f"(c[3])
        : "r"(a[0]), "r"(a[1]), "r"(a[2]), "r"(a[3]), "r"(b[0]), "r"(b[1]));
}

// ---------------- dtype detect + degree init (merged) ----------------
__global__ void k_detect_init(const int* __restrict__ w, int n_words) {
    int i = blockIdx.x * blockDim.x + threadIdx.x;
    if (i < NN) g_deg[i] = 1;  // self loop
    if (blockIdx.x == 0) {
        __shared__ int nz;
        if (threadIdx.x == 0) nz = 0;
        __syncthreads();
        for (int k = threadIdx.x; k < 2048; k += blockDim.x) {
            int idx = 2 * k + 1;
            if (idx < n_words && w[idx] != 0) atomicAdd(&nz, 1);
        }
        __syncthreads();
        if (threadIdx.x == 0) g_is64 = (nz == 0) ? 1 : 0;
    }
}

__device__ __forceinline__ int read_ei(const void* p, long long i) {
    if (g_is64) return (int)((const long long*)p)[i];
    return ((const int*)p)[i];
}

__global__ void k_hist(const void* __restrict__ ei, int E) {
    int i = blockIdx.x * blockDim.x + threadIdx.x;
    if (i < E) {
        int d = read_ei(ei, (long long)E + i);
        if (d >= 0 && d < NN) atomicAdd(&g_deg[d], 1);
    }
}

// ---- 3-phase full-chip exclusive scan ----
__global__ void k_scan_partial() {
    __shared__ int sh[SCAN_BLK];
    int t = threadIdx.x;
    int i = blockIdx.x * SCAN_BLK + t;
    int v = (i < NN) ? g_deg[i] : 0;
    sh[t] = v;
    __syncthreads();
    for (int off = SCAN_BLK / 2; off > 0; off >>= 1) {
        if (t < off) sh[t] += sh[t + off];
        __syncthreads();
    }
    if (t == 0) g_bsum[blockIdx.x] = sh[0];
}

__global__ void k_scan_bsum() {
    __shared__ int sh[128];
    int t = threadIdx.x;
    int v = (t < SCAN_NBLK) ? g_bsum[t] : 0;
    sh[t] = v;
    __syncthreads();
    for (int off = 1; off < 128; off <<= 1) {
        int u = (t >= off) ? sh[t - off] : 0;
        __syncthreads();
        sh[t] += u;
        __syncthreads();
    }
    if (t < SCAN_NBLK) g_boff[t] = sh[t] - v;
    if (t == 127) g_offs[NN] = sh[127];
}

__global__ void k_scan_final() {
    __shared__ int sh[SCAN_BLK];
    int t = threadIdx.x;
    int i = blockIdx.x * SCAN_BLK + t;
    int v = (i < NN) ? g_deg[i] : 0;
    sh[t] = v;
    __syncthreads();
    for (int off = 1; off < SCAN_BLK; off <<= 1) {
        int u = (t >= off) ? sh[t - off] : 0;
        __syncthreads();
        sh[t] += u;
        __syncthreads();
    }
    if (i < NN) {
        int ex = sh[t] - v + g_boff[blockIdx.x];
        g_offs[i]   = ex;
        g_cursor[i] = ex;
    }
}

__global__ void k_fill(const void* __restrict__ ei, int E, int EP) {
    int i = blockIdx.x * blockDim.x + threadIdx.x;
    if (i >= EP) return;
    int s, d;
    if (i < E) {
        s = read_ei(ei, i);
        d = read_ei(ei, (long long)E + i);
    } else {
        s = d = i - E;
    }
    if (d < 0 || d >= NN || s < 0 || s >= NN) return;
    int pos = atomicAdd(&g_cursor[d], 1);
    g_csr[pos] = s;
}

// ---------------- GEMM1 (tensor cores, tf32) + fused s1/d1 ----------------
// block: 128 rows x 64 cols, 256 threads (8 warps), warp = 16-row stripe.
__global__ void k_gemm1_tc(const float* __restrict__ x, const float* __restrict__ W,
                           const float* __restrict__ as, const float* __restrict__ ad) {
    __shared__ unsigned ws[DIN][72];  // tf32 bits of W1 [k][n], padded: conflict-free
    int t    = threadIdx.x;
    int lane = t & 31;
    int warp = t >> 5;
    int m0   = blockIdx.x * 128;

    for (int i = t; i < DIN * DHID; i += 256) {
        int k = i >> 6, n = i & 63;
        ws[k][n] = f2tf32(W[k * DHID + n]);
    }
    __syncthreads();

    int r0 = m0 + warp * 16 + (lane >> 2);  // rows r0 and r0+8
    bool v0 = r0 < NN, v1 = (r0 + 8) < NN;
    const float* xp0 = x + (size_t)r0 * DIN + (lane & 3);
    const float* xp1 = xp0 + (size_t)8 * DIN;

    float c[8][4];
#pragma unroll
    for (int nc = 0; nc < 8; ++nc)
#pragma unroll
        for (int j = 0; j < 4; ++j) c[nc][j] = 0.f;

#pragma unroll
    for (int kc = 0; kc < 16; ++kc) {
        int ko = kc * 8;
        unsigned a[4];
        a[0] = v0 ? f2tf32(__ldg(&xp0[ko]))     : 0u;
        a[1] = v1 ? f2tf32(__ldg(&xp1[ko]))     : 0u;
        a[2] = v0 ? f2tf32(__ldg(&xp0[ko + 4])) : 0u;
        a[3] = v1 ? f2tf32(__ldg(&xp1[ko + 4])) : 0u;
#pragma unroll
        for (int nc = 0; nc < 8; ++nc) {
            unsigned b[2];
            b[0] = ws[ko + (lane & 3)][nc * 8 + (lane >> 2)];
            b[1] = ws[ko + (lane & 3) + 4][nc * 8 + (lane >> 2)];
            mma_tf32(c[nc], a, b);
        }
    }

    // epilogue: store h1 + fused s1/d1 dot products
    float slo = 0.f, shi = 0.f, dlo = 0.f, dhi = 0.f;
#pragma unroll
    for (int nc = 0; nc < 8; ++nc) {
        int col = nc * 8 + 2 * (lane & 3);
        float as0 = as[col], as1 = as[col + 1];
        float ad0 = ad[col], ad1 = ad[col + 1];
        slo += c[nc][0] * as0 + c[nc][1] * as1;
        dlo += c[nc][0] * ad0 + c[nc][1] * ad1;
        shi += c[nc][2] * as0 + c[nc][3] * as1;
        dhi += c[nc][2] * ad0 + c[nc][3] * ad1;
        if (v0) *(float2*)&g_h1[(size_t)r0 * DHID + col]       = make_float2(c[nc][0], c[nc][1]);
        if (v1) *(float2*)&g_h1[(size_t)(r0 + 8) * DHID + col] = make_float2(c[nc][2], c[nc][3]);
    }
    // reduce over the 4 lanes of each row quad (xor 1, 2)
    slo += __shfl_xor_sync(0xffffffffu, slo, 1); slo += __shfl_xor_sync(0xffffffffu, slo, 2);
    dlo += __shfl_xor_sync(0xffffffffu, dlo, 1); dlo += __shfl_xor_sync(0xffffffffu, dlo, 2);
    shi += __shfl_xor_sync(0xffffffffu, shi, 1); shi += __shfl_xor_sync(0xffffffffu, shi, 2);
    dhi += __shfl_xor_sync(0xffffffffu, dhi, 1); dhi += __shfl_xor_sync(0xffffffffu, dhi, 2);
    if ((lane & 3) == 0) {
        if (v0) { g_s1[r0] = slo;     g_d1[r0] = dlo; }
        if (v1) { g_s1[r0 + 8] = shi; g_d1[r0 + 8] = dhi; }
    }
}

// ---------------- layer-1 GAT: warp per dst node ----------------
__global__ void k_edge64(const float* __restrict__ bias) {
    int w    = (blockIdx.x * blockDim.x + threadIdx.x) >> 5;
    int lane = threadIdx.x & 31;
    if (w >= NN) return;
    int beg = g_offs[w], end = g_offs[w + 1];
    float dv = g_d1[w];

    float m = -1e30f;
    for (int j = beg + lane; j < end; j += 32) {
        int si  = g_csr[j];
        float e = g_s1[si] + dv;
        e = (e > 0.f) ? e : NEG * e;
        g_e[j] = e;
        m = fmaxf(m, e);
    }
#pragma unroll
    for (int o = 16; o; o >>= 1) m = fmaxf(m, __shfl_xor_sync(0xffffffffu, m, o));

    float denom = 0.f, acc0 = 0.f, acc1 = 0.f;
    for (int base = beg; base < end; base += 32) {
        int j = base + lane;
        float ex = 0.f;
        int si = 0;
        if (j < end) { ex = __expf(g_e[j] - m); si = g_csr[j]; }
        denom += ex;
        int cnt = min(32, end - base);
        int t = 0;
        for (; t + 4 <= cnt; t += 4) {
            float e0 = __shfl_sync(0xffffffffu, ex, t + 0);
            float e1 = __shfl_sync(0xffffffffu, ex, t + 1);
            float e2 = __shfl_sync(0xffffffffu, ex, t + 2);
            float e3 = __shfl_sync(0xffffffffu, ex, t + 3);
            int   s0 = __shfl_sync(0xffffffffu, si, t + 0);
            int   s1 = __shfl_sync(0xffffffffu, si, t + 1);
            int   s2 = __shfl_sync(0xffffffffu, si, t + 2);
            int   s3 = __shfl_sync(0xffffffffu, si, t + 3);
            const float* p0 = g_h1 + (size_t)s0 * DHID;
            const float* p1 = g_h1 + (size_t)s1 * DHID;
            const float* p2 = g_h1 + (size_t)s2 * DHID;
            const float* p3 = g_h1 + (size_t)s3 * DHID;
            float x00 = p0[lane], x01 = p0[lane + 32];
            float x10 = p1[lane], x11 = p1[lane + 32];
            float x20 = p2[lane], x21 = p2[lane + 32];
            float x30 = p3[lane], x31 = p3[lane + 32];
            acc0 = fmaf(e0, x00, acc0); acc1 = fmaf(e0, x01, acc1);
            acc0 = fmaf(e1, x10, acc0); acc1 = fmaf(e1, x11, acc1);
            acc0 = fmaf(e2, x20, acc0); acc1 = fmaf(e2, x21, acc1);
            acc0 = fmaf(e3, x30, acc0); acc1 = fmaf(e3, x31, acc1);
        }
        for (; t < cnt; ++t) {
            float ej = __shfl_sync(0xffffffffu, ex, t);
            int   sj = __shfl_sync(0xffffffffu, si, t);
            const float* p = g_h1 + (size_t)sj * DHID;
            acc0 = fmaf(ej, p[lane], acc0);
            acc1 = fmaf(ej, p[lane + 32], acc1);
        }
    }
#pragma unroll
    for (int o = 16; o; o >>= 1) denom += __shfl_xor_sync(0xffffffffu, denom, o);

    float inv = 1.f / denom;
    float o0 = acc0 * inv + bias[lane];
    float o1 = acc1 * inv + bias[lane + 32];
    o0 = (o0 > 0.f) ? o0 : expm1f(o0);
    o1 = (o1 > 0.f) ? o1 : expm1f(o1);
    g_out1[(size_t)w * DHID + lane]      = o0;
    g_out1[(size_t)w * DHID + 32 + lane] = o1;
}

// ---------------- layer 2: h2 = out1 @ W2 + s2/d2 ----------------
__global__ void k_gemm2sd(const float* __restrict__ W2,
                          const float* __restrict__ as, const float* __restrict__ ad) {
    int w    = (blockIdx.x * blockDim.x + threadIdx.x) >> 5;
    int lane = threadIdx.x & 31;
    if (w >= NN) return;
    float h0 = g_out1[(size_t)w * DHID + lane];
    float h1 = g_out1[(size_t)w * DHID + 32 + lane];
    float p[DOUT];
#pragma unroll
    for (int c = 0; c < DOUT; ++c)
        p[c] = h0 * W2[lane * DOUT + c] + h1 * W2[(lane + 32) * DOUT + c];
#pragma unroll
    for (int c = 0; c < DOUT; ++c)
#pragma unroll
        for (int o = 16; o; o >>= 1) p[c] += __shfl_xor_sync(0xffffffffu, p[c], o);
    if (lane == 0) {
        float s = 0.f, d = 0.f;
#pragma unroll
        for (int c = 0; c < DOUT; ++c) {
            g_h2[(size_t)w * DOUT + c] = p[c];
            s += p[c] * as[c];
            d += p[c] * ad[c];
        }
        g_s2[w] = s;
        g_d2[w] = d;
    }
}

// ---------------- layer-2 GAT (C=6) ----------------
__global__ void k_edge6(const float* __restrict__ b2, float* __restrict__ out) {
    int w    = (blockIdx.x * blockDim.x + threadIdx.x) >> 5;
    int lane = threadIdx.x & 31;
    if (w >= NN) return;
    int beg = g_offs[w], end = g_offs[w + 1];
    float dv = g_d2[w];

    float m = -1e30f;
    for (int j = beg + lane; j < end; j += 32) {
        int si  = g_csr[j];
        float e = g_s2[si] + dv;
        e = (e > 0.f) ? e : NEG * e;
        g_e[j] = e;
        m = fmaxf(m, e);
    }
#pragma unroll
    for (int o = 16; o; o >>= 1) m = fmaxf(m, __shfl_xor_sync(0xffffffffu, m, o));

    float denom = 0.f;
    float a0 = 0.f, a1 = 0.f, a2 = 0.f, a3 = 0.f, a4 = 0.f, a5 = 0.f;
    for (int j = beg + lane; j < end; j += 32) {
        int si   = g_csr[j];
        float ex = __expf(g_e[j] - m);
        denom += ex;
        const float2* hp = (const float2*)g_h2 + (size_t)si * 3;
        float2 v0 = hp[0], v1 = hp[1], v2 = hp[2];
        a0 = fmaf(ex, v0.x, a0); a1 = fmaf(ex, v0.y, a1);
        a2 = fmaf(ex, v1.x, a2); a3 = fmaf(ex, v1.y, a3);
        a4 = fmaf(ex, v2.x, a4); a5 = fmaf(ex, v2.y, a5);
    }
#pragma unroll
    for (int o = 16; o; o >>= 1) {
        denom += __shfl_xor_sync(0xffffffffu, denom, o);
        a0 += __shfl_xor_sync(0xffffffffu, a0, o);
        a1 += __shfl_xor_sync(0xffffffffu, a1, o);
        a2 += __shfl_xor_sync(0xffffffffu, a2, o);
        a3 += __shfl_xor_sync(0xffffffffu, a3, o);
        a4 += __shfl_xor_sync(0xffffffffu, a4, o);
        a5 += __shfl_xor_sync(0xffffffffu, a5, o);
    }
    if (lane == 0) {
        float inv = 1.f / denom;
        out[(size_t)w * DOUT + 0] = a0 * inv + b2[0];
        out[(size_t)w * DOUT + 1] = a1 * inv + b2[1];
        out[(size_t)w * DOUT + 2] = a2 * inv + b2[2];
        out[(size_t)w * DOUT + 3] = a3 * inv + b2[3];
        out[(size_t)w * DOUT + 4] = a4 * inv + b2[4];
        out[(size_t)w * DOUT + 5] = a5 * inv + b2[5];
    }
}

// ---------------- launch ----------------
extern "C" void kernel_launch(void* const* d_in, const int* in_sizes, int n_in,
                              void* d_out, int out_size) {
    const float* x      = (const float*)d_in[0];
    const void*  ei     = d_in[1];
    const float* W1     = (const float*)d_in[2];
    const float* a_src1 = (const float*)d_in[3];
    const float* a_dst1 = (const float*)d_in[4];
    const float* b1     = (const float*)d_in[5];
    const float* W2     = (const float*)d_in[6];
    const float* a_src2 = (const float*)d_in[7];
    const float* a_dst2 = (const float*)d_in[8];
    const float* b2     = (const float*)d_in[9];
    float*       out    = (float*)d_out;

    int E  = in_sizes[1] / 2;
    int EP = E + NN;
    int n_words = in_sizes[1];

    // CSR build
    k_detect_init<<<(NN + 255) / 256, 256>>>((const int*)ei, n_words);
    k_hist<<<(E + 255) / 256, 256>>>(ei, E);
    k_scan_partial<<<SCAN_NBLK, SCAN_BLK>>>();
    k_scan_bsum<<<1, 128>>>();
    k_scan_final<<<SCAN_NBLK, SCAN_BLK>>>();
    k_fill<<<(EP + 255) / 256, 256>>>(ei, E, EP);

    // layer 1 (tensor-core GEMM + fused s1/d1)
    k_gemm1_tc<<<(NN + 127) / 128, 256>>>(x, W1, a_src1, a_dst1);
    int warp_blocks = (NN * 32 + 255) / 256;
    k_edge64<<<warp_blocks, 256>>>(b1);

    // layer 2
    k_gemm2sd<<<warp_blocks, 256>>>(W2, a_src2, a_dst2);
    k_edge6<<<warp_blocks, 256>>>(b2, out);
}

// round 7
// speedup vs baseline: 2.0679x; 1.1015x over previous
#include <cuda_runtime.h>

#define NN    100000
#define DIN   128
#define DHID  64
#define DOUT  6
#define EMAX  1600000
#define EPMAX (EMAX + NN)
#define NEG   0.2f

// ---------------- static device scratch ----------------
__device__ float g_h1[(size_t)NN * DHID];
__device__ float g_h2[(size_t)NN * DOUT];
__device__ float g_s1[NN], g_d1[NN];
__device__ float g_s2[NN], g_d2[NN];
__device__ int   g_deg[NN];
__device__ int   g_beg[NN];
__device__ int   g_cursor[NN];
__device__ int   g_csr[EPMAX];
__device__ float g_e[EPMAX];
__device__ int   g_is64;
__device__ int   g_total;

// ---------------- tf32 helpers ----------------
__device__ __forceinline__ unsigned f2tf32(float f) {
    unsigned r;
    asm("cvt.rna.tf32.f32 %0, %1;" : "=r"(r) : "f"(f));
    return r;
}

__device__ __forceinline__ void mma_tf32(float* c, const unsigned* a, const unsigned* b) {
    asm volatile(
        "mma.sync.aligned.m16n8k8.row.col.f32.tf32.tf32.f32 "
        "{%0,%1,%2,%3}, {%4,%5,%6,%7}, {%8,%9}, {%0,%1,%2,%3};"
        : "+f"(c[0]), "+f"(c[1]), "+f"(c[2]), "+f"(c[3])
        : "r"(a[0]), "r"(a[1]), "r"(a[2]), "r"(a[3]), "r"(b[0]), "r"(b[1]));
}

// ---------------- dtype detect + degree init + total reset (merged) ----------------
__global__ void k_detect_init(const int* __restrict__ w, int n_words) {
    int i = blockIdx.x * blockDim.x + threadIdx.x;
    if (i < NN) g_deg[i] = 1;  // self loop
    if (i == 0) g_total = 0;
    if (blockIdx.x == 0) {
        __shared__ int nz;
        if (threadIdx.x == 0) nz = 0;
        __syncthreads();
        for (int k = threadIdx.x; k < 2048; k += blockDim.x) {
            int idx = 2 * k + 1;
            if (idx < n_words && w[idx] != 0) atomicAdd(&nz, 1);
        }
        __syncthreads();
        if (threadIdx.x == 0) g_is64 = (nz == 0) ? 1 : 0;
    }
}

__device__ __forceinline__ int read_ei(const void* p, long long i) {
    if (g_is64) return (int)((const long long*)p)[i];
    return ((const int*)p)[i];
}

__global__ void k_hist(const void* __restrict__ ei, int E) {
    int i = blockIdx.x * blockDim.x + threadIdx.x;
    if (i < E) {
        int d = read_ei(ei, (long long)E + i);
        if (d >= 0 && d < NN) atomicAdd(&g_deg[d], 1);
    }
}

// segment assignment via atomic bump (replaces 3-phase prefix scan)
__global__ void k_assign() {
    int i = blockIdx.x * blockDim.x + threadIdx.x;
    if (i < NN) {
        int deg = g_deg[i];
        int beg = atomicAdd(&g_total, deg);
        g_beg[i]    = beg;
        g_cursor[i] = beg;
    }
}

__global__ void k_fill(const void* __restrict__ ei, int E, int EP) {
    int i = blockIdx.x * blockDim.x + threadIdx.x;
    if (i >= EP) return;
    int s, d;
    if (i < E) {
        s = read_ei(ei, i);
        d = read_ei(ei, (long long)E + i);
    } else {
        s = d = i - E;
    }
    if (d < 0 || d >= NN || s < 0 || s >= NN) return;
    int pos = atomicAdd(&g_cursor[d], 1);
    g_csr[pos] = s;
}

// ---------------- GEMM1 (tensor cores, tf32) + fused s1/d1 ----------------
__global__ void k_gemm1_tc(const float* __restrict__ x, const float* __restrict__ W,
                           const float* __restrict__ as, const float* __restrict__ ad) {
    __shared__ unsigned ws[DIN][72];
    int t    = threadIdx.x;
    int lane = t & 31;
    int warp = t >> 5;
    int m0   = blockIdx.x * 128;

    for (int i = t; i < DIN * DHID; i += 256) {
        int k = i >> 6, n = i & 63;
        ws[k][n] = f2tf32(W[k * DHID + n]);
    }
    __syncthreads();

    int r0 = m0 + warp * 16 + (lane >> 2);
    bool v0 = r0 < NN, v1 = (r0 + 8) < NN;
    const float* xp0 = x + (size_t)r0 * DIN + (lane & 3);
    const float* xp1 = xp0 + (size_t)8 * DIN;

    float c[8][4];
#pragma unroll
    for (int nc = 0; nc < 8; ++nc)
#pragma unroll
        for (int j = 0; j < 4; ++j) c[nc][j] = 0.f;

#pragma unroll
    for (int kc = 0; kc < 16; ++kc) {
        int ko = kc * 8;
        unsigned a[4];
        a[0] = v0 ? f2tf32(__ldg(&xp0[ko]))     : 0u;
        a[1] = v1 ? f2tf32(__ldg(&xp1[ko]))     : 0u;
        a[2] = v0 ? f2tf32(__ldg(&xp0[ko + 4])) : 0u;
        a[3] = v1 ? f2tf32(__ldg(&xp1[ko + 4])) : 0u;
#pragma unroll
        for (int nc = 0; nc < 8; ++nc) {
            unsigned b[2];
            b[0] = ws[ko + (lane & 3)][nc * 8 + (lane >> 2)];
            b[1] = ws[ko + (lane & 3) + 4][nc * 8 + (lane >> 2)];
            mma_tf32(c[nc], a, b);
        }
    }

    float slo = 0.f, shi = 0.f, dlo = 0.f, dhi = 0.f;
#pragma unroll
    for (int nc = 0; nc < 8; ++nc) {
        int col = nc * 8 + 2 * (lane & 3);
        float as0 = as[col], as1 = as[col + 1];
        float ad0 = ad[col], ad1 = ad[col + 1];
        slo += c[nc][0] * as0 + c[nc][1] * as1;
        dlo += c[nc][0] * ad0 + c[nc][1] * ad1;
        shi += c[nc][2] * as0 + c[nc][3] * as1;
        dhi += c[nc][2] * ad0 + c[nc][3] * ad1;
        if (v0) *(float2*)&g_h1[(size_t)r0 * DHID + col]       = make_float2(c[nc][0], c[nc][1]);
        if (v1) *(float2*)&g_h1[(size_t)(r0 + 8) * DHID + col] = make_float2(c[nc][2], c[nc][3]);
    }
    slo += __shfl_xor_sync(0xffffffffu, slo, 1); slo += __shfl_xor_sync(0xffffffffu, slo, 2);
    dlo += __shfl_xor_sync(0xffffffffu, dlo, 1); dlo += __shfl_xor_sync(0xffffffffu, dlo, 2);
    shi += __shfl_xor_sync(0xffffffffu, shi, 1); shi += __shfl_xor_sync(0xffffffffu, shi, 2);
    dhi += __shfl_xor_sync(0xffffffffu, dhi, 1); dhi += __shfl_xor_sync(0xffffffffu, dhi, 2);
    if ((lane & 3) == 0) {
        if (v0) { g_s1[r0] = slo;     g_d1[r0] = dlo; }
        if (v1) { g_s1[r0 + 8] = shi; g_d1[r0 + 8] = dhi; }
    }
}

// ---------------- layer-1 GAT + fused layer-2 linear (h2/s2/d2) ----------------
__global__ void k_edge64(const float* __restrict__ bias, const float* __restrict__ W2,
                         const float* __restrict__ as2, const float* __restrict__ ad2) {
    int w    = (blockIdx.x * blockDim.x + threadIdx.x) >> 5;
    int lane = threadIdx.x & 31;
    if (w >= NN) return;
    int beg = g_beg[w], end = beg + g_deg[w];
    float dv = g_d1[w];

    // pass 1: logits + max
    float m = -1e30f;
    for (int j = beg + lane; j < end; j += 32) {
        int si  = g_csr[j];
        float e = g_s1[si] + dv;
        e = (e > 0.f) ? e : NEG * e;
        g_e[j] = e;
        m = fmaxf(m, e);
    }
#pragma unroll
    for (int o = 16; o; o >>= 1) m = fmaxf(m, __shfl_xor_sync(0xffffffffu, m, o));

    // pass 2: exp, denom, weighted gather-accumulate
    float denom = 0.f, acc0 = 0.f, acc1 = 0.f;
    for (int base = beg; base < end; base += 32) {
        int j = base + lane;
        float ex = 0.f;
        int si = 0;
        if (j < end) { ex = __expf(g_e[j] - m); si = g_csr[j]; }
        denom += ex;
        int cnt = min(32, end - base);
        int t = 0;
        for (; t + 4 <= cnt; t += 4) {
            float e0 = __shfl_sync(0xffffffffu, ex, t + 0);
            float e1 = __shfl_sync(0xffffffffu, ex, t + 1);
            float e2 = __shfl_sync(0xffffffffu, ex, t + 2);
            float e3 = __shfl_sync(0xffffffffu, ex, t + 3);
            int   s0 = __shfl_sync(0xffffffffu, si, t + 0);
            int   s1 = __shfl_sync(0xffffffffu, si, t + 1);
            int   s2 = __shfl_sync(0xffffffffu, si, t + 2);
            int   s3 = __shfl_sync(0xffffffffu, si, t + 3);
            const float* p0 = g_h1 + (size_t)s0 * DHID;
            const float* p1 = g_h1 + (size_t)s1 * DHID;
            const float* p2 = g_h1 + (size_t)s2 * DHID;
            const float* p3 = g_h1 + (size_t)s3 * DHID;
            float x00 = p0[lane], x01 = p0[lane + 32];
            float x10 = p1[lane], x11 = p1[lane + 32];
            float x20 = p2[lane], x21 = p2[lane + 32];
            float x30 = p3[lane], x31 = p3[lane + 32];
            acc0 = fmaf(e0, x00, acc0); acc1 = fmaf(e0, x01, acc1);
            acc0 = fmaf(e1, x10, acc0); acc1 = fmaf(e1, x11, acc1);
            acc0 = fmaf(e2, x20, acc0); acc1 = fmaf(e2, x21, acc1);
            acc0 = fmaf(e3, x30, acc0); acc1 = fmaf(e3, x31, acc1);
        }
        for (; t < cnt; ++t) {
            float ej = __shfl_sync(0xffffffffu, ex, t);
            int   sj = __shfl_sync(0xffffffffu, si, t);
            const float* p = g_h1 + (size_t)sj * DHID;
            acc0 = fmaf(ej, p[lane], acc0);
            acc1 = fmaf(ej, p[lane + 32], acc1);
        }
    }
#pragma unroll
    for (int o = 16; o; o >>= 1) denom += __shfl_xor_sync(0xffffffffu, denom, o);

    float inv = 1.f / denom;
    float o0 = acc0 * inv + bias[lane];
    float o1 = acc1 * inv + bias[lane + 32];
    o0 = (o0 > 0.f) ? o0 : expm1f(o0);  // ELU
    o1 = (o1 > 0.f) ? o1 : expm1f(o1);

    // fused layer-2 linear: h2[w] = out1row @ W2, s2/d2 dots
    float p[DOUT];
#pragma unroll
    for (int c = 0; c < DOUT; ++c)
        p[c] = o0 * W2[lane * DOUT + c] + o1 * W2[(lane + 32) * DOUT + c];
#pragma unroll
    for (int c = 0; c < DOUT; ++c)
#pragma unroll
        for (int o = 16; o; o >>= 1) p[c] += __shfl_xor_sync(0xffffffffu, p[c], o);
    if (lane == 0) {
        float s = 0.f, d = 0.f;
#pragma unroll
        for (int c = 0; c < DOUT; ++c) {
            g_h2[(size_t)w * DOUT + c] = p[c];
            s += p[c] * as2[c];
            d += p[c] * ad2[c];
        }
        g_s2[w] = s;
        g_d2[w] = d;
    }
}

// ---------------- layer-2 GAT (C=6) ----------------
__global__ void k_edge6(const float* __restrict__ b2, float* __restrict__ out) {
    int w    = (blockIdx.x * blockDim.x + threadIdx.x) >> 5;
    int lane = threadIdx.x & 31;
    if (w >= NN) return;
    int beg = g_beg[w], end = beg + g_deg[w];
    float dv = g_d2[w];

    float m = -1e30f;
    for (int j = beg + lane; j < end; j += 32) {
        int si  = g_csr[j];
        float e = g_s2[si] + dv;
        e = (e > 0.f) ? e : NEG * e;
        g_e[j] = e;
        m = fmaxf(m, e);
    }
#pragma unroll
    for (int o = 16; o; o >>= 1) m = fmaxf(m, __shfl_xor_sync(0xffffffffu, m, o));

    float denom = 0.f;
    float a0 = 0.f, a1 = 0.f, a2 = 0.f, a3 = 0.f, a4 = 0.f, a5 = 0.f;
    for (int j = beg + lane; j < end; j += 32) {
        int si   = g_csr[j];
        float ex = __expf(g_e[j] - m);
        denom += ex;
        const float2* hp = (const float2*)g_h2 + (size_t)si * 3;
        float2 v0 = hp[0], v1 = hp[1], v2 = hp[2];
        a0 = fmaf(ex, v0.x, a0); a1 = fmaf(ex, v0.y, a1);
        a2 = fmaf(ex, v1.x, a2); a3 = fmaf(ex, v1.y, a3);
        a4 = fmaf(ex, v2.x, a4); a5 = fmaf(ex, v2.y, a5);
    }
#pragma unroll
    for (int o = 16; o; o >>= 1) {
        denom += __shfl_xor_sync(0xffffffffu, denom, o);
        a0 += __shfl_xor_sync(0xffffffffu, a0, o);
        a1 += __shfl_xor_sync(0xffffffffu, a1, o);
        a2 += __shfl_xor_sync(0xffffffffu, a2, o);
        a3 += __shfl_xor_sync(0xffffffffu, a3, o);
        a4 += __shfl_xor_sync(0xffffffffu, a4, o);
        a5 += __shfl_xor_sync(0xffffffffu, a5, o);
    }
    if (lane == 0) {
        float inv = 1.f / denom;
        out[(size_t)w * DOUT + 0] = a0 * inv + b2[0];
        out[(size_t)w * DOUT + 1] = a1 * inv + b2[1];
        out[(size_t)w * DOUT + 2] = a2 * inv + b2[2];
        out[(size_t)w * DOUT + 3] = a3 * inv + b2[3];
        out[(size_t)w * DOUT + 4] = a4 * inv + b2[4];
        out[(size_t)w * DOUT + 5] = a5 * inv + b2[5];
    }
}

// ---------------- launch ----------------
extern "C" void kernel_launch(void* const* d_in, const int* in_sizes, int n_in,
                              void* d_out, int out_size) {
    const float* x      = (const float*)d_in[0];
    const void*  ei     = d_in[1];
    const float* W1     = (const float*)d_in[2];
    const float* a_src1 = (const float*)d_in[3];
    const float* a_dst1 = (const float*)d_in[4];
    const float* b1     = (const float*)d_in[5];
    const float* W2     = (const float*)d_in[6];
    const float* a_src2 = (const float*)d_in[7];
    const float* a_dst2 = (const float*)d_in[8];
    const float* b2     = (const float*)d_in[9];
    float*       out    = (float*)d_out;

    int E  = in_sizes[1] / 2;
    int EP = E + NN;
    int n_words = in_sizes[1];

    // CSR build (4 launches)
    k_detect_init<<<(NN + 255) / 256, 256>>>((const int*)ei, n_words);
    k_hist<<<(E + 255) / 256, 256>>>(ei, E);
    k_assign<<<(NN + 255) / 256, 256>>>();
    k_fill<<<(EP + 255) / 256, 256>>>(ei, E, EP);

    // layer 1 GEMM (tensor cores) + fused s1/d1
    k_gemm1_tc<<<(NN + 127) / 128, 256>>>(x, W1, a_src1, a_dst1);

    // layer-1 GAT + fused layer-2 linear
    int warp_blocks = (NN * 32 + 255) / 256;
    k_edge64<<<warp_blocks, 256>>>(b1, W2, a_src2, a_dst2);

    // layer-2 GAT
    k_edge6<<<warp_blocks, 256>>>(b2, out);
}